// round 3
// baseline (speedup 1.0000x reference)
#include <cuda_runtime.h>

// Problem constants
// x1d: [1,128,256,256], mask: [1,128,256]
// L,R: [m=128][n=256][32]  -> stored as [m][n*32+c] (8192 cols)
// out: [1,256,256,128] fp32

#define FULL_MASK 0xffffffffu

__device__ float g_L[128 * 8192];
__device__ float g_R[128 * 8192];

// ---------- packed f32x2 helpers (Blackwell FFMA2) ----------
__device__ __forceinline__ void fma2(unsigned long long &d, unsigned long long a,
                                     unsigned long long b) {
#if __CUDA_ARCH__ >= 1000
    asm("fma.rn.f32x2 %0, %1, %2, %0;" : "+l"(d) : "l"(a), "l"(b));
#else
    float2 *dd = reinterpret_cast<float2 *>(&d);
    const float2 *aa = reinterpret_cast<const float2 *>(&a);
    const float2 *bb = reinterpret_cast<const float2 *>(&b);
    dd->x = fmaf(aa->x, bb->x, dd->x);
    dd->y = fmaf(aa->y, bb->y, dd->y);
#endif
}
__device__ __forceinline__ unsigned long long bcast2(float a) {
    unsigned long long r;
    asm("mov.b64 %0, {%1,%1};" : "=l"(r) : "f"(a));
    return r;
}
__device__ __forceinline__ unsigned long long mk2(float x, float y) {
    unsigned long long r;
    asm("mov.b64 %0, {%1,%2};" : "=l"(r) : "f"(x), "f"(y));
    return r;
}
__device__ __forceinline__ float2 unpack2(unsigned long long v) {
    float2 r;
    asm("mov.b64 {%0,%1}, %2;" : "=f"(r.x), "=f"(r.y) : "l"(v));
    return r;
}

// =====================================================================
// Kernel 1: LayerNorm + left/right projections (+mask)
// grid = 1024 blocks, each handles 32 rows of the 32768 (m,n) rows.
// =====================================================================
__global__ __launch_bounds__(256) void k1_ln_proj(
    const float *__restrict__ x, const float *__restrict__ mask,
    const float *__restrict__ norm_w, const float *__restrict__ norm_b,
    const float *__restrict__ wl, const float *__restrict__ bl,
    const float *__restrict__ wr, const float *__restrict__ br) {
    extern __shared__ float sm[];
    float *sw = sm;           // [256][64]  (wl | wr)
    float *sb = sw + 16384;   // [64]
    float *snw = sb + 64;     // [256]
    float *snb = snw + 256;   // [256]
    float *sxn = snb + 256;   // [32][256]

    const int t = threadIdx.x;

    for (int idx = t; idx < 16384; idx += 256) {
        int k = idx >> 6, c = idx & 63;
        sw[idx] = (c < 32) ? wl[k * 32 + c] : wr[k * 32 + c - 32];
    }
    if (t < 64) sb[t] = (t < 32) ? bl[t] : br[t - 32];
    snw[t] = norm_w[t];
    snb[t] = norm_b[t];
    __syncthreads();

    const int row0 = blockIdx.x * 32;

    // ---- Phase A: LayerNorm, one warp per 4 rows ----
    {
        const int warp = t >> 5, lane = t & 31;
#pragma unroll
        for (int rr = 0; rr < 4; rr++) {
            const int lrow = warp * 4 + rr;
            const float4 *xr = (const float4 *)(x + (size_t)(row0 + lrow) * 256);
            float4 v0 = xr[lane];
            float4 v1 = xr[32 + lane];
            float s1 = v0.x + v0.y + v0.z + v0.w + v1.x + v1.y + v1.z + v1.w;
            float s2 = v0.x * v0.x + v0.y * v0.y + v0.z * v0.z + v0.w * v0.w +
                       v1.x * v1.x + v1.y * v1.y + v1.z * v1.z + v1.w * v1.w;
#pragma unroll
            for (int off = 16; off; off >>= 1) {
                s1 += __shfl_xor_sync(FULL_MASK, s1, off);
                s2 += __shfl_xor_sync(FULL_MASK, s2, off);
            }
            float mu = s1 * (1.f / 256.f);
            float var = s2 * (1.f / 256.f) - mu * mu;
            float inv = rsqrtf(var + 1e-5f);
            int k0 = lane * 4, k1 = 128 + lane * 4;
            float4 n0, n1;
            n0.x = (v0.x - mu) * inv * snw[k0 + 0] + snb[k0 + 0];
            n0.y = (v0.y - mu) * inv * snw[k0 + 1] + snb[k0 + 1];
            n0.z = (v0.z - mu) * inv * snw[k0 + 2] + snb[k0 + 2];
            n0.w = (v0.w - mu) * inv * snw[k0 + 3] + snb[k0 + 3];
            n1.x = (v1.x - mu) * inv * snw[k1 + 0] + snb[k1 + 0];
            n1.y = (v1.y - mu) * inv * snw[k1 + 1] + snb[k1 + 1];
            n1.z = (v1.z - mu) * inv * snw[k1 + 2] + snb[k1 + 2];
            n1.w = (v1.w - mu) * inv * snw[k1 + 3] + snb[k1 + 3];
            ((float4 *)(sxn + lrow * 256))[lane] = n0;
            ((float4 *)(sxn + lrow * 256))[32 + lane] = n1;
        }
    }
    __syncthreads();

    // ---- Phase B: GEMM 32x64, K=256 ----
    const int tr = t >> 5;       // 0..7 -> 4 rows each
    const int c2 = t & 31;       // 2 output channels: c2*2, c2*2+1
    unsigned long long acc[4] = {0ull, 0ull, 0ull, 0ull};
    const float *xr0 = sxn + tr * 4 * 256;
#pragma unroll 8
    for (int k = 0; k < 256; k++) {
        unsigned long long wv =
            *(const unsigned long long *)(sw + k * 64 + c2 * 2);
#pragma unroll
        for (int i = 0; i < 4; i++) {
            unsigned long long aa = bcast2(xr0[i * 256 + k]);
            fma2(acc[i], aa, wv);
        }
    }
    float2 bv = *(const float2 *)(sb + c2 * 2);
#pragma unroll
    for (int i = 0; i < 4; i++) {
        int gr = row0 + tr * 4 + i;
        float mv = mask[gr];
        float2 a = unpack2(acc[i]);
        float2 o;
        o.x = (a.x + bv.x) * mv;
        o.y = (a.y + bv.y) * mv;
        int m = gr >> 8, n = gr & 255;
        if (c2 < 16)
            *(float2 *)(g_L + (size_t)m * 8192 + n * 32 + c2 * 2) = o;
        else
            *(float2 *)(g_R + (size_t)m * 8192 + n * 32 + (c2 - 16) * 2) = o;
    }
}

// =====================================================================
// Kernel 2: fused outer-product contraction + final projection
// grid = (64, 64): CTA (bi,bj) handles i in [bi*4,bi*4+4), j in [bj*4,bj*4+4)
//   Stage 1: S[jy][ix] (128x128) = sum_m R[m][jbase+jy]*L[m][ibase+ix]
//   Stage 2: out[i,j,o] = (sum_k S[..]*wf[k][o] + bf[o]) / (norm+1e-3)
// =====================================================================
__global__ __launch_bounds__(256, 2) void k2_opm(
    const float *__restrict__ mask, const float *__restrict__ wf,
    const float *__restrict__ bf, float *__restrict__ out) {
    extern __shared__ float sm[];
    float *sS = sm;                 // [128][128]
    float *sAB = sm + 16384;        // stage1: As[16][128] | Bs[16][128]; stage2: sW[64][128]
    float *snorm = sm + 16384 + 8192;  // [16]

    const int t = threadIdx.x;
    const int bi = blockIdx.x, bj = blockIdx.y;
    const int ibase = bi * 128, jbase = bj * 128;

    // ---- pair norms: norm[p] = sum_m mask[m,gi]*mask[m,gj] ----
    {
        int p = t >> 4, l = t & 15;
        int gi = bi * 4 + (p >> 2), gj = bj * 4 + (p & 3);
        float s = 0.f;
#pragma unroll
        for (int mm = 0; mm < 8; mm++) {
            int m = l + mm * 16;
            s += mask[m * 256 + gi] * mask[m * 256 + gj];
        }
#pragma unroll
        for (int off = 8; off; off >>= 1) s += __shfl_down_sync(FULL_MASK, s, off);
        if (l == 0) snorm[p] = s;
    }

    // ---- Stage 1 ----
    float *As = sAB;            // R chunk [16][128] (jy)
    float *Bs = sAB + 2048;     // L chunk [16][128] (ix)
    const int ty = t >> 4, tx = t & 15;
    unsigned long long acc[8][4];
#pragma unroll
    for (int i = 0; i < 8; i++)
#pragma unroll
        for (int j = 0; j < 4; j++) acc[i][j] = 0ull;

    for (int k0 = 0; k0 < 128; k0 += 16) {
#pragma unroll
        for (int h = 0; h < 2; h++) {
            int fidx = t + 256 * h;
            int kk = fidx >> 5, c4 = (fidx & 31) << 2;
            ((float4 *)As)[fidx] =
                *(const float4 *)(g_R + (size_t)(k0 + kk) * 8192 + jbase + c4);
            ((float4 *)Bs)[fidx] =
                *(const float4 *)(g_L + (size_t)(k0 + kk) * 8192 + ibase + c4);
        }
        __syncthreads();
#pragma unroll
        for (int kk = 0; kk < 16; kk++) {
            float4 a0 = *(const float4 *)(As + kk * 128 + ty * 4);
            float4 a1 = *(const float4 *)(As + kk * 128 + 64 + ty * 4);
            float4 b0 = *(const float4 *)(Bs + kk * 128 + tx * 4);
            float4 b1 = *(const float4 *)(Bs + kk * 128 + 64 + tx * 4);
            unsigned long long bp[4];
            bp[0] = mk2(b0.x, b0.y);
            bp[1] = mk2(b0.z, b0.w);
            bp[2] = mk2(b1.x, b1.y);
            bp[3] = mk2(b1.z, b1.w);
            float av[8] = {a0.x, a0.y, a0.z, a0.w, a1.x, a1.y, a1.z, a1.w};
#pragma unroll
            for (int i = 0; i < 8; i++) {
                unsigned long long aa = bcast2(av[i]);
#pragma unroll
                for (int j = 0; j < 4; j++) fma2(acc[i][j], aa, bp[j]);
            }
        }
        __syncthreads();
    }
    // write S to smem: rows {ty*4+i, 64+ty*4+i}, cols {tx*4..+3, 64+tx*4..+3}
#pragma unroll
    for (int i = 0; i < 8; i++) {
        int row = (i < 4) ? (ty * 4 + i) : (64 + ty * 4 + (i - 4));
        float2 v0 = unpack2(acc[i][0]);
        float2 v1 = unpack2(acc[i][1]);
        float2 v2 = unpack2(acc[i][2]);
        float2 v3 = unpack2(acc[i][3]);
        float4 q0 = make_float4(v0.x, v0.y, v1.x, v1.y);
        float4 q1 = make_float4(v2.x, v2.y, v3.x, v3.y);
        *(float4 *)(sS + row * 128 + tx * 4) = q0;
        *(float4 *)(sS + row * 128 + 64 + tx * 4) = q1;
    }
    __syncthreads();

    // ---- Stage 2 ----
    // thread -> pair p = t>>4 (16 pairs), oh = t&15; outputs o = oh*2 + 32*c, c=0..3
    float *sW = sAB;  // [64][128]
    const int oh = t & 15;
    const int p = t >> 4;
    const int ii = p >> 2, jj = p & 3;
    const int sbase = jj * 4096 + ii * 32;
    unsigned long long r2[4] = {0ull, 0ull, 0ull, 0ull};

    for (int kc0 = 0; kc0 < 1024; kc0 += 64) {
#pragma unroll
        for (int h = 0; h < 8; h++) {
            int fidx = t + 256 * h;
            ((float4 *)sW)[fidx] = ((const float4 *)wf)[kc0 * 32 + fidx];
        }
        __syncthreads();
#pragma unroll 8
        for (int kk = 0; kk < 64; kk++) {
            int k = kc0 + kk;
            int koff = ((k & 31) << 7) + (k >> 5);  // y*128 + x
            unsigned long long aa = bcast2(sS[sbase + koff]);
            const float *wrow = sW + kk * 128 + oh * 2;
            fma2(r2[0], aa, *(const unsigned long long *)(wrow));
            fma2(r2[1], aa, *(const unsigned long long *)(wrow + 32));
            fma2(r2[2], aa, *(const unsigned long long *)(wrow + 64));
            fma2(r2[3], aa, *(const unsigned long long *)(wrow + 96));
        }
        __syncthreads();
    }

    // ---- epilogue ----
    const int gi = bi * 4 + ii, gj = bj * 4 + jj;
    const float inv = 1.f / (snorm[p] + 0.001f);
    float *obase = out + ((size_t)gi * 256 + gj) * 128;
#pragma unroll
    for (int c = 0; c < 4; c++) {
        int o0 = oh * 2 + 32 * c;
        float2 a = unpack2(r2[c]);
        float2 bb = *(const float2 *)(bf + o0);
        float2 ov;
        ov.x = (a.x + bb.x) * inv;
        ov.y = (a.y + bb.y) * inv;
        *(float2 *)(obase + o0) = ov;
    }
}

// =====================================================================
extern "C" void kernel_launch(void *const *d_in, const int *in_sizes, int n_in,
                              void *d_out, int out_size) {
    const float *x = (const float *)d_in[0];
    const float *mask = (const float *)d_in[1];
    const float *norm_w = (const float *)d_in[2];
    const float *norm_b = (const float *)d_in[3];
    const float *wl = (const float *)d_in[4];
    const float *bl = (const float *)d_in[5];
    const float *wr = (const float *)d_in[6];
    const float *br = (const float *)d_in[7];
    const float *wf = (const float *)d_in[8];
    const float *bf = (const float *)d_in[9];
    float *out = (float *)d_out;

    const int smem1 = (16384 + 64 + 256 + 256 + 8192) * 4;  // 100608 B
    const int smem2 = (16384 + 8192 + 16) * 4;              // 98368 B
    cudaFuncSetAttribute(k1_ln_proj, cudaFuncAttributeMaxDynamicSharedMemorySize, smem1);
    cudaFuncSetAttribute(k2_opm, cudaFuncAttributeMaxDynamicSharedMemorySize, smem2);

    k1_ln_proj<<<1024, 256, smem1>>>(x, mask, norm_w, norm_b, wl, bl, wr, br);
    dim3 g2(64, 64);
    k2_opm<<<g2, 256, smem2>>>(mask, wf, bf, out);
}

// round 5
// speedup vs baseline: 2.7601x; 2.7601x over previous
#include <cuda_runtime.h>
#include <cstdint>

#define FULL_MASK 0xffffffffu

// scratch: K-major transposed projections (tf32, k-permuted per 8-group) and wf
__device__ float g_Lt[8192 * 128];   // [col = n*32 + x][m permuted]
__device__ float g_Rt[8192 * 128];   // [col = n*32 + y][m permuted]
__device__ float g_wfT[128 * 1024];  // [o][k permuted]

// ------------------------- helpers -------------------------
__device__ __forceinline__ uint32_t smem_u32(const void *p) {
    uint32_t a;
    asm("{ .reg .u64 t; cvta.to.shared.u64 t, %1; cvt.u32.u64 %0, t; }"
        : "=r"(a) : "l"(p));
    return a;
}
__device__ __forceinline__ uint32_t to_tf32(float f) {
    uint32_t u;
    asm("cvt.rna.tf32.f32 %0, %1;" : "=r"(u) : "f"(f));
    return u;
}
__device__ __forceinline__ void cpa16(uint32_t dst, const void *src) {
    asm volatile("cp.async.ca.shared.global [%0], [%1], 16;"
                 :: "r"(dst), "l"(src));
}
#define CP_COMMIT() asm volatile("cp.async.commit_group;" ::: "memory")
#define CP_WAIT(n) asm volatile("cp.async.wait_group %0;" :: "n"(n) : "memory")

__device__ __forceinline__ void mma8(float *c, uint2 a01, uint2 a23, uint2 b) {
    asm volatile(
        "mma.sync.aligned.m16n8k8.row.col.f32.tf32.tf32.f32 "
        "{%0,%1,%2,%3}, {%4,%5,%6,%7}, {%8,%9}, {%0,%1,%2,%3};"
        : "+f"(c[0]), "+f"(c[1]), "+f"(c[2]), "+f"(c[3])
        : "r"(a01.x), "r"(a23.x), "r"(a01.y), "r"(a23.y),
          "r"(b.x), "r"(b.y));
}

// k-permutation within 8-groups: pos(k) = (k&~7) + (k&3)*2 + ((k>>2)&1)
// inverse within group: d(e) = (e>>1) + 4*(e&1)

// =====================================================================
// Kernel 0: transpose wf [1024][128] -> g_wfT [128][1024] (tf32, permuted)
// =====================================================================
__global__ __launch_bounds__(256) void k0_wft(const float *__restrict__ wf) {
    __shared__ float Tk[32 * 130];
    const int t = threadIdx.x;
    const int b = blockIdx.x;  // k-chunk 0..31
#pragma unroll
    for (int it = 0; it < 16; it++) {
        int f = t + it * 256;       // 0..4095
        int kk = f >> 7, o = f & 127;
        Tk[kk * 130 + o] = wf[(size_t)(b * 32 + kk) * 128 + o];
    }
    __syncthreads();
#pragma unroll
    for (int it = 0; it < 4; it++) {
        int f4 = t + it * 256;      // 0..1023
        int o = f4 >> 3, kq = f4 & 7;
        uint4 v;
        uint32_t *vv = (uint32_t *)&v;
#pragma unroll
        for (int e4 = 0; e4 < 4; e4++) {
            int e = (kq & 1) * 4 + e4;
            int d = (e >> 1) + 4 * (e & 1);
            int kk = (kq >> 1) * 8 + d;  // local k 0..31
            vv[e4] = to_tf32(Tk[kk * 130 + o]);
        }
        *(uint4 *)(g_wfT + (size_t)o * 1024 + b * 32 + kq * 4) = v;
    }
}

// =====================================================================
// Kernel 1: LayerNorm + projections -> g_Lt/g_Rt (tf32, m-permuted)
// grid = 1024: block b -> mc = b>>8 (m-chunk of 32), n = b&255.
// =====================================================================
__global__ __launch_bounds__(256) void k1_ln_proj(
    const float *__restrict__ x, const float *__restrict__ mask,
    const float *__restrict__ norm_w, const float *__restrict__ norm_b,
    const float *__restrict__ wl, const float *__restrict__ bl,
    const float *__restrict__ wr, const float *__restrict__ br) {
    extern __shared__ float sm[];
    float *sw = sm;           // [256][64]
    float *sb = sw + 16384;   // [64]
    float *snw = sb + 64;     // [256]
    float *snb = snw + 256;   // [256]
    float *sxn = snb + 256;   // [32][256] (reused as T[64][36])

    const int t = threadIdx.x;
    for (int idx = t; idx < 16384; idx += 256) {
        int k = idx >> 6, c = idx & 63;
        sw[idx] = (c < 32) ? wl[k * 32 + c] : wr[k * 32 + c - 32];
    }
    if (t < 64) sb[t] = (t < 32) ? bl[t] : br[t - 32];
    snw[t] = norm_w[t];
    snb[t] = norm_b[t];
    __syncthreads();

    const int mc = blockIdx.x >> 8;
    const int n = blockIdx.x & 255;

    {
        const int warp = t >> 5, lane = t & 31;
#pragma unroll
        for (int rr = 0; rr < 4; rr++) {
            const int lrow = warp * 4 + rr;
            const int m = mc * 32 + lrow;
            const float4 *xr = (const float4 *)(x + ((size_t)m * 256 + n) * 256);
            float4 v0 = xr[lane];
            float4 v1 = xr[32 + lane];
            float s1 = v0.x + v0.y + v0.z + v0.w + v1.x + v1.y + v1.z + v1.w;
            float s2 = v0.x * v0.x + v0.y * v0.y + v0.z * v0.z + v0.w * v0.w +
                       v1.x * v1.x + v1.y * v1.y + v1.z * v1.z + v1.w * v1.w;
#pragma unroll
            for (int off = 16; off; off >>= 1) {
                s1 += __shfl_xor_sync(FULL_MASK, s1, off);
                s2 += __shfl_xor_sync(FULL_MASK, s2, off);
            }
            float mu = s1 * (1.f / 256.f);
            float var = s2 * (1.f / 256.f) - mu * mu;
            float inv = rsqrtf(var + 1e-5f);
            int k0 = lane * 4, k1i = 128 + lane * 4;
            float4 n0, n1;
            n0.x = (v0.x - mu) * inv * snw[k0 + 0] + snb[k0 + 0];
            n0.y = (v0.y - mu) * inv * snw[k0 + 1] + snb[k0 + 1];
            n0.z = (v0.z - mu) * inv * snw[k0 + 2] + snb[k0 + 2];
            n0.w = (v0.w - mu) * inv * snw[k0 + 3] + snb[k0 + 3];
            n1.x = (v1.x - mu) * inv * snw[k1i + 0] + snb[k1i + 0];
            n1.y = (v1.y - mu) * inv * snw[k1i + 1] + snb[k1i + 1];
            n1.z = (v1.z - mu) * inv * snw[k1i + 2] + snb[k1i + 2];
            n1.w = (v1.w - mu) * inv * snw[k1i + 3] + snb[k1i + 3];
            ((float4 *)(sxn + lrow * 256))[lane] = n0;
            ((float4 *)(sxn + lrow * 256))[32 + lane] = n1;
        }
    }
    __syncthreads();

    const int tr = t >> 5;
    const int c2 = t & 31;
    float2 acc[4] = {{0, 0}, {0, 0}, {0, 0}, {0, 0}};
    const float *xr0 = sxn + tr * 4 * 256;
#pragma unroll 8
    for (int k = 0; k < 256; k++) {
        float2 wv = *(const float2 *)(sw + k * 64 + c2 * 2);
#pragma unroll
        for (int i = 0; i < 4; i++) {
            float a = xr0[i * 256 + k];
            acc[i].x = fmaf(a, wv.x, acc[i].x);
            acc[i].y = fmaf(a, wv.y, acc[i].y);
        }
    }
    float2 bv = *(const float2 *)(sb + c2 * 2);
    float2 ov[4];
#pragma unroll
    for (int i = 0; i < 4; i++) {
        int m = mc * 32 + tr * 4 + i;
        float mv = mask[m * 256 + n];
        ov[i].x = (acc[i].x + bv.x) * mv;
        ov[i].y = (acc[i].y + bv.y) * mv;
    }
    __syncthreads();
    float *T = sxn;  // [64][36]
    {
        int ch = (c2 < 16) ? (c2 * 2) : (32 + (c2 - 16) * 2);
#pragma unroll
        for (int i = 0; i < 4; i++) {
            int ml = tr * 4 + i;
            T[ch * 36 + ml] = ov[i].x;
            T[(ch + 1) * 36 + ml] = ov[i].y;
        }
    }
    __syncthreads();
    {
        int ch = t >> 2;
        int m0 = (t * 8) & 31;   // group-aligned (0,8,16,24)
        float v[8];
#pragma unroll
        for (int d = 0; d < 8; d++) v[d] = T[ch * 36 + m0 + d];
        // permuted store: position e holds d(e) = (e>>1)+4*(e&1)
        uint4 q0, q1;
        q0.x = to_tf32(v[0]); q0.y = to_tf32(v[4]);
        q0.z = to_tf32(v[1]); q0.w = to_tf32(v[5]);
        q1.x = to_tf32(v[2]); q1.y = to_tf32(v[6]);
        q1.z = to_tf32(v[3]); q1.w = to_tf32(v[7]);
        float *dst = ((ch < 32) ? g_Lt : g_Rt) +
                     (size_t)(n * 32 + (ch & 31)) * 128 + mc * 32 + m0;
        *(uint4 *)dst = q0;
        *(uint4 *)(dst + 4) = q1;
    }
}

// =====================================================================
// Kernel 2: fused outer-product (stage B) + projection (stage C), tf32 HMMA
// grid = (64, 32): CTA (bi, bj2): i-block bi (128 ix), j-blocks jb=bj2*2+g.
// =====================================================================
// smem layout (bytes):
//   0      : snorm[32] floats
//   1024   : buf0 (A 18432 | B 18432)   tile rows: 144B (32k tf32 + 16B pad)
//   37888  : buf1 (A 18432 | B 18432)
//   75776  : S' [32 p][1028 floats] stride 4112B     (131584 B)
// total 207360
#define OFF_SP 75776
#define SP_STRIDE 4112
#define TROW 144

__global__ __launch_bounds__(256, 1) void k2_opm(
    const float *__restrict__ mask, const float *__restrict__ bf,
    float *__restrict__ out) {
    extern __shared__ __align__(1024) char smem[];
    const uint32_t sb32 = smem_u32(smem);
    const int t = threadIdx.x, w = t >> 5, lane = t & 31;
    const int rb = lane >> 2, q = lane & 3;
    const int bi = blockIdx.x, bj2 = blockIdx.y;
    float *snorm = (float *)smem;
    const int OA[2] = {1024, 37888};

    // ---- pair norms ----
    {
        int p = t >> 3, l = t & 7;
        int g = p >> 4, ii = (p >> 2) & 3, jj = p & 3;
        int gi = bi * 4 + ii, gj = (bj2 * 2 + g) * 4 + jj;
        float s = 0.f;
#pragma unroll
        for (int mm = 0; mm < 16; mm++) {
            int m = l + mm * 8;
            s += mask[m * 256 + gi] * mask[m * 256 + gj];
        }
        s += __shfl_down_sync(FULL_MASK, s, 4);
        s += __shfl_down_sync(FULL_MASK, s, 2);
        s += __shfl_down_sync(FULL_MASK, s, 1);
        if (l == 0) snorm[p] = s;
    }

    // ================= Stage B =================
    // chunk loader: A = R rows (jy), B = L rows (ix); 128 rows x 32 m-k each
    auto loadB = [&](int buf, int g, int mcv) {
        int jb = bj2 * 2 + g;
        uint32_t dA = sb32 + OA[buf], dB = dA + 18432;
#pragma unroll
        for (int i = 0; i < 4; i++) {
            int u = t + i * 256;          // 16B unit 0..1023
            int row = u >> 3, qq = u & 7;
            cpa16(dA + row * TROW + qq * 16,
                  g_Rt + (size_t)(jb * 128 + row) * 128 + mcv * 32 + qq * 4);
            cpa16(dB + row * TROW + qq * 16,
                  g_Lt + (size_t)(bi * 128 + row) * 128 + mcv * 32 + qq * 4);
        }
    };

    const int wm = w >> 1, wn = w & 1;  // warp tile: M rows jy 32, N cols ix 64
    loadB(0, 0, 0);
    CP_COMMIT();

    for (int g = 0; g < 2; g++) {
        float acc[2][8][4];
#pragma unroll
        for (int a = 0; a < 2; a++)
#pragma unroll
            for (int b = 0; b < 8; b++)
#pragma unroll
                for (int c = 0; c < 4; c++) acc[a][b][c] = 0.f;

        for (int mcv = 0; mcv < 4; mcv++) {
            const int c = g * 4 + mcv, buf = c & 1;
            if (c < 7) {
                int nc = c + 1;
                loadB(nc & 1, nc >> 2, nc & 3);
                CP_COMMIT();
                CP_WAIT(1);
            } else {
                CP_WAIT(0);
            }
            __syncthreads();
            const char *A = smem + OA[buf];
            const char *B = smem + OA[buf] + 18432;
#pragma unroll
            for (int s = 0; s < 4; s++) {
                uint2 afr[2][2];
#pragma unroll
                for (int mt = 0; mt < 2; mt++) {
                    int r = wm * 32 + mt * 16 + rb;
                    afr[mt][0] = *(const uint2 *)(A + r * TROW + s * 32 + q * 8);
                    afr[mt][1] =
                        *(const uint2 *)(A + (r + 8) * TROW + s * 32 + q * 8);
                }
#pragma unroll
                for (int nt = 0; nt < 8; nt++) {
                    int n = wn * 64 + nt * 8 + rb;
                    uint2 b = *(const uint2 *)(B + n * TROW + s * 32 + q * 8);
                    mma8(acc[0][nt], afr[0][0], afr[0][1], b);
                    mma8(acc[1][nt], afr[1][0], afr[1][1], b);
                }
            }
            __syncthreads();
        }
        // write S'_g (tf32-rounded), permuted k positions
#pragma unroll
        for (int mt = 0; mt < 2; mt++)
#pragma unroll
            for (int nt = 0; nt < 8; nt++)
#pragma unroll
                for (int cr = 0; cr < 4; cr++) {
                    int jy = wm * 32 + mt * 16 + rb + ((cr >= 2) ? 8 : 0);
                    int ix = wn * 64 + nt * 8 + q * 2 + (cr & 1);
                    int p = g * 16 + (ix >> 5) * 4 + (jy >> 5);
                    int k = (ix & 31) * 32 + (jy & 31);
                    int pos = (k & ~7) + (k & 3) * 2 + ((k >> 2) & 1);
                    *(uint32_t *)(smem + OFF_SP + p * SP_STRIDE + pos * 4) =
                        to_tf32(acc[mt][nt][cr]);
                }
        __syncthreads();
    }

    // ================= Stage C =================
    // out^T[o 128][p 32] = sum_k wfT[o][k] * S'[p][k]; warp w: M tile o=w*16
    auto loadC = [&](int buf, int ct) {
        uint32_t dA = sb32 + OA[buf];
#pragma unroll
        for (int i = 0; i < 2; i++) {
            int u = t + i * 256;          // 16B unit 0..511? need 1024 units/8 per row...
            int row = u >> 2, qq = u & 3; // 128 rows x 4 x 16B? 32 floats = 8 units!
            (void)row; (void)qq;
        }
        // 128 rows x 8 units of 16B = 1024 units
#pragma unroll
        for (int i = 0; i < 4; i++) {
            int u = t + i * 256;
            int row = u >> 3, qq = u & 7;
            cpa16(dA + row * TROW + qq * 16,
                  g_wfT + (size_t)row * 1024 + ct * 32 + qq * 4);
        }
    };

    loadC(0, 0);
    CP_COMMIT();
    float cc[4][4];
#pragma unroll
    for (int a = 0; a < 4; a++)
#pragma unroll
        for (int b = 0; b < 4; b++) cc[a][b] = 0.f;

    for (int ct = 0; ct < 32; ct++) {
        const int buf = ct & 1;
        if (ct < 31) {
            loadC(1 - buf, ct + 1);
            CP_COMMIT();
            CP_WAIT(1);
        } else {
            CP_WAIT(0);
        }
        __syncthreads();
        const char *A = smem + OA[buf];
#pragma unroll
        for (int s = 0; s < 4; s++) {
            int r = w * 16 + rb;
            uint2 a0 = *(const uint2 *)(A + r * TROW + s * 32 + q * 8);
            uint2 a1 = *(const uint2 *)(A + (r + 8) * TROW + s * 32 + q * 8);
#pragma unroll
            for (int nt = 0; nt < 4; nt++) {
                int n = nt * 8 + rb;
                uint2 b = *(const uint2 *)(smem + OFF_SP + n * SP_STRIDE +
                                           (ct * 32 + s * 8 + q * 2) * 4);
                mma8(cc[nt], a0, a1, b);
            }
        }
        __syncthreads();
    }

    // ---- epilogue: stage through smem, bias + norm, coalesced store ----
    float *sOut = (float *)(smem + OA[0] + 18432);  // [32 p][128 o]
#pragma unroll
    for (int nt = 0; nt < 4; nt++)
#pragma unroll
        for (int cr = 0; cr < 4; cr++) {
            int o = w * 16 + rb + ((cr >= 2) ? 8 : 0);
            int p = nt * 8 + q * 2 + (cr & 1);
            sOut[p * 128 + o] = cc[nt][cr];
        }
    __syncthreads();
#pragma unroll
    for (int i = 0; i < 4; i++) {
        int u = t + i * 256;          // float4 unit 0..1023
        int p = u >> 5, o4 = (u & 31) * 4;
        int g = p >> 4, iiv = (p >> 2) & 3, jjv = p & 3;
        int gi = bi * 4 + iiv, gj = (bj2 * 2 + g) * 4 + jjv;
        float inv = 1.f / (snorm[p] + 0.001f);
        float4 v = *(float4 *)(sOut + p * 128 + o4);
        float4 bb = *(const float4 *)(bf + o4);
        v.x = (v.x + bb.x) * inv;
        v.y = (v.y + bb.y) * inv;
        v.z = (v.z + bb.z) * inv;
        v.w = (v.w + bb.w) * inv;
        *(float4 *)(out + ((size_t)gi * 256 + gj) * 128 + o4) = v;
    }
}

// =====================================================================
extern "C" void kernel_launch(void *const *d_in, const int *in_sizes, int n_in,
                              void *d_out, int out_size) {
    const float *x = (const float *)d_in[0];
    const float *mask = (const float *)d_in[1];
    const float *norm_w = (const float *)d_in[2];
    const float *norm_b = (const float *)d_in[3];
    const float *wl = (const float *)d_in[4];
    const float *bl = (const float *)d_in[5];
    const float *wr = (const float *)d_in[6];
    const float *br = (const float *)d_in[7];
    const float *wf = (const float *)d_in[8];
    const float *bf = (const float *)d_in[9];
    float *out = (float *)d_out;

    const int smem1 = (16384 + 64 + 256 + 256 + 8192) * 4;  // 100608 B
    const int smem2 = 207360;
    cudaFuncSetAttribute(k1_ln_proj, cudaFuncAttributeMaxDynamicSharedMemorySize, smem1);
    cudaFuncSetAttribute(k2_opm, cudaFuncAttributeMaxDynamicSharedMemorySize, smem2);

    k0_wft<<<32, 256>>>(wf);
    k1_ln_proj<<<1024, 256, smem1>>>(x, mask, norm_w, norm_b, wl, bl, wr, br);
    dim3 g2(64, 32);
    k2_opm<<<g2, 256, smem2>>>(mask, bf, out);
}